// round 3
// baseline (speedup 1.0000x reference)
#include <cuda_runtime.h>
#include <math.h>
#include <stdint.h>

#define V_N   50000
#define E_N   800000
#define TE    128
#define TILES (E_N / TE)   /* 6250 */

// smem word offsets
#define FH_OFF   0                       /* frot hi: [128][36] b32 (bf16x2 pairs + pad) */
#define FL_OFF   (128 * 36)              /* frot lo */
#define BAS_OFF  (FL_OFF + 128 * 36)     /* basis:   [128][8] f32 */
#define MSG_OFF  (BAS_OFF + 128 * 8)     /* msg:     [128][68] f32 */
#define SMEM_WORDS (MSG_OFF + 128 * 68)  /* 18944 words = 75776 B */

__device__ float g_agg[(size_t)V_N * 64];

__global__ void zero_agg_kernel() {
    size_t i = (size_t)blockIdx.x * blockDim.x + threadIdx.x;
    size_t n4 = (size_t)V_N * 64 / 4;
    if (i < n4) reinterpret_cast<float4*>(g_agg)[i] = make_float4(0.f, 0.f, 0.f, 0.f);
}

// pack two f32 into bf16x2: e0 -> low half, e1 -> high half
__device__ __forceinline__ uint32_t pack_bf16(float e0, float e1) {
    uint32_t r;
    asm("cvt.rn.bf16x2.f32 %0, %1, %2;" : "=r"(r) : "f"(e1), "f"(e0));
    return r;
}

__device__ __forceinline__ void mma_bf16(float* d, const uint32_t* a, const uint32_t* b) {
    asm volatile(
        "mma.sync.aligned.m16n8k16.row.col.f32.bf16.bf16.f32 "
        "{%0,%1,%2,%3}, {%4,%5,%6,%7}, {%8,%9}, {%0,%1,%2,%3};"
        : "+f"(d[0]), "+f"(d[1]), "+f"(d[2]), "+f"(d[3])
        : "r"(a[0]), "r"(a[1]), "r"(a[2]), "r"(a[3]), "r"(b[0]), "r"(b[1]));
}

// Persistent CTAs, 256 threads = 8 warps. Per 128-edge tile:
//   build: gather x[src], per-irrep rotate, bf16 hi/lo split -> smem frot; basis -> smem
//   mma:   tmp[128, 320] = frot[128,64] @ W'[320,64]^T  (B in regs, 3-product bf16 split),
//          basis-contract in epilogue -> msg[128,64] in smem
//   scatter: red.global.add.v4 of msg rows into g_agg[tgt]
__global__ __launch_bounds__(256, 1) void edge_mma_kernel(
    const float* __restrict__ x,
    const int*   __restrict__ ei,
    const float* __restrict__ angles,
    const float* __restrict__ trans,
    const float* __restrict__ Wn)
{
    extern __shared__ uint32_t sm[];
    float* smf = reinterpret_cast<float*>(sm);

    const int tid  = threadIdx.x;
    const int lane = tid & 31;
    const int wid  = tid >> 5;
    const int g    = lane >> 2;   // group id (row / n-col within fragment)
    const int t    = lane & 3;    // thread-in-group

    // ---- B fragments in registers, persistent across all tiles ----
    // B col-major (k, n): element = W_neigh[b][ocol][k], ocol = 8*wid + g.
    // b-frag reg0: k = 2t,2t+1 ; reg1: k = 2t+8,2t+9  (within 16k block ks)
    uint32_t bh[5][4][2], bl[5][4][2];
    {
        const int ocol = 8 * wid + g;
#pragma unroll
        for (int b = 0; b < 5; ++b)
#pragma unroll
            for (int ks = 0; ks < 4; ++ks)
#pragma unroll
                for (int r = 0; r < 2; ++r) {
                    const float2 w = *reinterpret_cast<const float2*>(
                        Wn + b * 4096 + ocol * 64 + 16 * ks + 2 * t + 8 * r);
                    uint32_t hi = pack_bf16(w.x, w.y);
                    float h0 = __uint_as_float(hi << 16);
                    float h1 = __uint_as_float(hi & 0xffff0000u);
                    uint32_t lo = pack_bf16(w.x - h0, w.y - h1);
                    bh[b][ks][r] = hi;
                    bl[b][ks][r] = lo;
                }
    }

    const int m0 = tid >> 1;      // edge row this thread builds
    const int h  = tid & 1;       // which 32-channel half

    for (int tile = blockIdx.x; tile < TILES; tile += gridDim.x) {
        // ---------------- build phase ----------------
        {
            const int e   = tile * TE + m0;
            const int src = ei[e];
            const float tr = trans[e];

            float4 f[8];
            const float4* xp = reinterpret_cast<const float4*>(x + (size_t)src * 64) + h * 8;
#pragma unroll
            for (int q = 0; q < 8; ++q) f[q] = xp[q];

            float s1, c1;
            __sincosf(tr, &s1, &c1);
            const float c2 = fmaf(2.f * c1, c1, -1.f);
            const float s2 = 2.f * s1 * c1;
#pragma unroll
            for (int q = 0; q < 8; ++q) {
                const bool r2 = (h == 1) && (q >= 4);
                const bool r1 = (h == 0) ? (q >= 4) : (q < 4);
                if (r1 || r2) {
                    const float cr = r2 ? c2 : c1, sr = r2 ? s2 : s1;
                    float a0 = f[q].x, a1 = f[q].y, a2 = f[q].z, a3 = f[q].w;
                    f[q].x = cr * a0 - sr * a1;
                    f[q].y = sr * a0 + cr * a1;
                    f[q].z = cr * a2 - sr * a3;
                    f[q].w = sr * a2 + cr * a3;
                }
            }
            const int base = m0 * 36 + h * 16;
#pragma unroll
            for (int q = 0; q < 8; ++q) {
                uint32_t h01 = pack_bf16(f[q].x, f[q].y);
                uint32_t h23 = pack_bf16(f[q].z, f[q].w);
                float l0 = f[q].x - __uint_as_float(h01 << 16);
                float l1 = f[q].y - __uint_as_float(h01 & 0xffff0000u);
                float l2 = f[q].z - __uint_as_float(h23 << 16);
                float l3 = f[q].w - __uint_as_float(h23 & 0xffff0000u);
                *reinterpret_cast<uint2*>(&sm[FH_OFF + base + 2 * q]) = make_uint2(h01, h23);
                *reinterpret_cast<uint2*>(&sm[FL_OFF + base + 2 * q]) =
                    make_uint2(pack_bf16(l0, l1), pack_bf16(l2, l3));
            }
            if (h == 0) {
                float sa, ca;
                __sincosf(angles[e], &sa, &ca);
                *reinterpret_cast<float4*>(&smf[BAS_OFF + m0 * 8]) =
                    make_float4(1.f, ca, sa, fmaf(2.f * ca, ca, -1.f));
                smf[BAS_OFF + m0 * 8 + 4] = 2.f * sa * ca;
            }
        }
        __syncthreads();

        // ---------------- mma + epilogue ----------------
#pragma unroll
        for (int m = 0; m < 8; ++m) {
            const int row = m * 16 + g;
            uint32_t ah[4][4], al[4][4];
#pragma unroll
            for (int ks = 0; ks < 4; ++ks) {
                const int c = 8 * ks + t;
                ah[ks][0] = sm[FH_OFF + row * 36 + c];
                ah[ks][1] = sm[FH_OFF + (row + 8) * 36 + c];
                ah[ks][2] = sm[FH_OFF + row * 36 + c + 4];
                ah[ks][3] = sm[FH_OFF + (row + 8) * 36 + c + 4];
                al[ks][0] = sm[FL_OFF + row * 36 + c];
                al[ks][1] = sm[FL_OFF + (row + 8) * 36 + c];
                al[ks][2] = sm[FL_OFF + row * 36 + c + 4];
                al[ks][3] = sm[FL_OFF + (row + 8) * 36 + c + 4];
            }
            float acc[5][4];
#pragma unroll
            for (int b = 0; b < 5; ++b) {
                acc[b][0] = acc[b][1] = acc[b][2] = acc[b][3] = 0.f;
            }
#pragma unroll
            for (int b = 0; b < 5; ++b)
#pragma unroll
                for (int ks = 0; ks < 4; ++ks) {
                    mma_bf16(acc[b], ah[ks], bh[b][ks]);
                    mma_bf16(acc[b], ah[ks], bl[b][ks]);
                    mma_bf16(acc[b], al[ks], bh[b][ks]);
                }
            // basis contraction (bas[0] == 1)
            const float4 ba  = *reinterpret_cast<const float4*>(&smf[BAS_OFF + row * 8]);
            const float  b4a = smf[BAS_OFF + row * 8 + 4];
            const float4 bb  = *reinterpret_cast<const float4*>(&smf[BAS_OFF + (row + 8) * 8]);
            const float  b4b = smf[BAS_OFF + (row + 8) * 8 + 4];
            float v0 = acc[0][0] + ba.y*acc[1][0] + ba.z*acc[2][0] + ba.w*acc[3][0] + b4a*acc[4][0];
            float v1 = acc[0][1] + ba.y*acc[1][1] + ba.z*acc[2][1] + ba.w*acc[3][1] + b4a*acc[4][1];
            float v2 = acc[0][2] + bb.y*acc[1][2] + bb.z*acc[2][2] + bb.w*acc[3][2] + b4b*acc[4][2];
            float v3 = acc[0][3] + bb.y*acc[1][3] + bb.z*acc[2][3] + bb.w*acc[3][3] + b4b*acc[4][3];
            const int col = 8 * wid + 2 * t;
            *reinterpret_cast<float2*>(&smf[MSG_OFF + row * 68 + col])       = make_float2(v0, v1);
            *reinterpret_cast<float2*>(&smf[MSG_OFF + (row + 8) * 68 + col]) = make_float2(v2, v3);
        }
        __syncthreads();

        // ---------------- scatter (fire-and-forget atomics) ----------------
        {
            const int r  = tid >> 1;
            const int ch = (tid & 1) * 32;
            const int tg = ei[E_N + tile * TE + r];
            float* ap = g_agg + (size_t)tg * 64 + ch;
            const float* mrow = &smf[MSG_OFF + r * 68 + ch];
#pragma unroll
            for (int j = 0; j < 8; ++j) {
                const float4 v = *reinterpret_cast<const float4*>(mrow + 4 * j);
                asm volatile("red.global.add.v4.f32 [%0], {%1,%2,%3,%4};"
                             :: "l"(ap + 4 * j), "f"(v.x), "f"(v.y), "f"(v.z), "f"(v.w)
                             : "memory");
            }
        }
        // no end-of-loop sync needed: next build touches frot/bas only; the
        // post-build __syncthreads orders this scatter before the next msg writes.
    }
}

// out = nonlin(LN(x @ K_self^T + agg)) + x
__global__ __launch_bounds__(256) void vertex_kernel(
    const float* __restrict__ x,
    const float* __restrict__ K_self,
    const float* __restrict__ gamma,
    const float* __restrict__ beta,
    float* __restrict__ out)
{
    __shared__ float Kt[64 * 64];      // Kt[i][o] = K_self[o][i]
    __shared__ float stage[8][64];

    int tid = threadIdx.x, lane = tid & 31, wid = tid >> 5;
    for (int idx = tid; idx < 4096; idx += 256) {
        int i = idx >> 6, o = idx & 63;
        Kt[idx] = K_self[o * 64 + i];
    }
    __syncthreads();

    float ga0 = gamma[2 * lane], ga1 = gamma[2 * lane + 1];
    float be0 = beta[2 * lane],  be1 = beta[2 * lane + 1];

    int nw = gridDim.x * 8;
    int gw = blockIdx.x * 8 + wid;
    float* st = stage[wid];

    for (int v = gw; v < V_N; v += nw) {
        const float* xr = x + (size_t)v * 64;
        st[lane]      = xr[lane];
        st[32 + lane] = xr[32 + lane];
        __syncwarp();

        float2 ag = *reinterpret_cast<const float2*>(g_agg + (size_t)v * 64 + 2 * lane);
        float acc0 = ag.x, acc1 = ag.y;
#pragma unroll 16
        for (int i = 0; i < 64; ++i) {
            float  xi = st[i];
            float2 w  = *reinterpret_cast<const float2*>(&Kt[(i << 6) + 2 * lane]);
            acc0 = fmaf(xi, w.x, acc0);
            acc1 = fmaf(xi, w.y, acc1);
        }

        float sum = acc0 + acc1;
        float ssq = acc0 * acc0 + acc1 * acc1;
#pragma unroll
        for (int o = 16; o; o >>= 1) {
            sum += __shfl_xor_sync(0xffffffffu, sum, o);
            ssq += __shfl_xor_sync(0xffffffffu, ssq, o);
        }
        float mu  = sum * (1.f / 64.f);
        float var = ssq * (1.f / 64.f) - mu * mu;
        float rs  = rsqrtf(var + 1e-5f);
        float h0  = (acc0 - mu) * rs * ga0 + be0;
        float h1  = (acc1 - mu) * rs * ga1 + be1;

        if (lane < 8) {
            h0 = fmaxf(h0, 0.f);
            h1 = fmaxf(h1, 0.f);
        } else {
            float n  = sqrtf(h0 * h0 + h1 * h1);
            n        = fmaxf(n, 1e-8f);
            float sp = (n > 20.f) ? n : log1pf(expf(n));
            float sc = sp / n;
            h0 *= sc;
            h1 *= sc;
        }

        float2 o2;
        o2.x = h0 + st[2 * lane];
        o2.y = h1 + st[2 * lane + 1];
        __syncwarp();
        *reinterpret_cast<float2*>(out + (size_t)v * 64 + 2 * lane) = o2;
    }
}

extern "C" void kernel_launch(void* const* d_in, const int* in_sizes, int n_in,
                              void* d_out, int out_size)
{
    const float* x      = (const float*)d_in[0];
    const int*   ei     = (const int*)  d_in[1];
    const float* angles = (const float*)d_in[2];
    const float* trans  = (const float*)d_in[3];
    const float* K_self = (const float*)d_in[4];
    const float* Wn     = (const float*)d_in[5];
    const float* gamma  = (const float*)d_in[6];
    const float* beta   = (const float*)d_in[7];
    float* out = (float*)d_out;

    (void)in_sizes; (void)n_in; (void)out_size;

    zero_agg_kernel<<<(V_N * 64 / 4 + 255) / 256, 256>>>();

    {
        const int shbytes = SMEM_WORDS * 4;   // 75776
        cudaFuncSetAttribute(edge_mma_kernel,
                             cudaFuncAttributeMaxDynamicSharedMemorySize, shbytes);
        edge_mma_kernel<<<148, 256, shbytes>>>(x, ei, angles, trans, Wn);
    }

    vertex_kernel<<<304, 256>>>(x, K_self, gamma, beta, out);
}